// round 17
// baseline (speedup 1.0000x reference)
#include <cuda_runtime.h>
#include <cstdint>

#define BB 8
#define HH 256
#define WW 256
#define NPIX (BB*HH*WW)
#define N_ITERS 200
#define TT 4                 // halo width / sub-iterations per exchange
#define NB (N_ITERS/TT)      // 50 exchange rounds (49 barriers)
#define NCTAS 256            // 8 images * (4x8) 32x64 tiles, 2 CTAs/SM
#define NTHREADS 288         // 36 column-pairs x 8 row groups
#define RPT 5                // rows per thread (x2 cols = 10 cells)
#define EXT_H 40
#define EXT_W 72

typedef unsigned long long u64;

// Double-buffered full-state exchange arrays (alloc-free scratch)
__device__ float gU [2][NPIX];
__device__ float gUB[2][NPIX];
__device__ float gP [2][NPIX];
__device__ float gQ [2][NPIX];

// Per-image barrier counters, one 128B line each (zero-initialized).
struct __align__(128) ImgLine { unsigned long long v; unsigned long long pad[15]; };
__device__ ImgLine g_arr[BB];

// ---- packed f32x2 helpers (sm_103a; min/max.f32x2 do NOT exist -> lane-wise clip) ----
__device__ __forceinline__ u64 pack2(float lo, float hi) {
    u64 r; asm("mov.b64 %0,{%1,%2};" : "=l"(r) : "f"(lo), "f"(hi)); return r;
}
__device__ __forceinline__ void unpack2(u64 v, float& lo, float& hi) {
    asm("mov.b64 {%0,%1},%2;" : "=f"(lo), "=f"(hi) : "l"(v));
}
__device__ __forceinline__ u64 fma2(u64 a, u64 b, u64 c) {
    u64 d; asm("fma.rn.f32x2 %0,%1,%2,%3;" : "=l"(d) : "l"(a), "l"(b), "l"(c)); return d;
}
__device__ __forceinline__ u64 add2(u64 a, u64 b) {
    u64 d; asm("add.rn.f32x2 %0,%1,%2;" : "=l"(d) : "l"(a), "l"(b)); return d;
}
__device__ __forceinline__ u64 mul2(u64 a, u64 b) {
    u64 d; asm("mul.rn.f32x2 %0,%1,%2;" : "=l"(d) : "l"(a), "l"(b)); return d;
}
// lane-wise clip to [-b, b]; bounds held as scalars (bn = -b precomputed)
__device__ __forceinline__ u64 clip2(u64 x, float b0, float b1, float n0, float n1) {
    float lo, hi; unpack2(x, lo, hi);
    lo = fminf(fmaxf(lo, n0), b0);
    hi = fminf(fmaxf(hi, n1), b1);
    return pack2(lo, hi);
}

__device__ __forceinline__ float ldcg(const float* p) {
    float v;
    asm volatile("ld.global.cg.f32 %0, [%1];" : "=f"(v) : "l"(p) : "memory");
    return v;
}
__device__ __forceinline__ u64 ld_acq(const unsigned long long* p) {
    u64 v;
    asm volatile("ld.acquire.gpu.global.u64 %0, [%1];" : "=l"(v) : "l"(p) : "memory");
    return v;
}
__device__ __forceinline__ void red_rel_add1(unsigned long long* p) {
    asm volatile("red.release.gpu.global.add.u64 [%0], %1;" :: "l"(p), "l"(1ULL) : "memory");
}

__global__ __launch_bounds__(NTHREADS, 2)
void tv_block(const float* __restrict__ f,
              const float* __restrict__ lam,
              float* __restrict__ out)
{
    const float SIG  = 0.35355339f;
    const float TAUc = 0.35355339f;
    const float INV  = 1.0f / (1.0f + TAUc);

    // Cross-thread arrays (identical to the 278us R13 kernel):
    __shared__ float ubE[EXT_H][37];   // ub of even ext col 2cp at [r][cp]; pad cp=36
    __shared__ float qO [EXT_H][38];   // q of odd ext col 2cp+1 at [r][cp+1]; pad [r][0]
    __shared__ float ubB[9][EXT_W];    // first-row ub of each row group; pad rg=8
    __shared__ float pB [9][EXT_W];    // last-row p of group at [rg+1][c]; pad row 0

    const int cta = blockIdx.x;
    const int img = cta >> 5;
    const int t   = cta & 31;
    const int i0  = (t >> 2) * 32;
    const int j0  = (t & 3) * 64;
    const int tid = threadIdx.x;
    const int cp  = tid % 36;          // column pair 0..35
    const int rg  = tid / 36;          // row group 0..7
    const int rb  = rg * RPT;
    const int c0  = 2 * cp;

    const int gi_top = i0 - TT + rb;
    const int gj0    = j0 - TT + c0;
    const int base   = (img * HH + gi_top) * WW + gj0;

    u64 epoch = 0;
    if (tid == 0) epoch = *(volatile unsigned long long*)&g_arr[img].v;

    // Zero all SMEM (pads stay 0 = finite garbage for ring math)
    for (int x = tid; x < EXT_H * 37; x += NTHREADS) ((float*)ubE)[x] = 0.f;
    for (int x = tid; x < EXT_H * 38; x += NTHREADS) ((float*)qO )[x] = 0.f;
    for (int x = tid; x < 9 * EXT_W;  x += NTHREADS) ((float*)ubB)[x] = 0.f;
    for (int x = tid; x < 9 * EXT_W;  x += NTHREADS) ((float*)pB )[x] = 0.f;

    // ---- packed per-pair state; clip bounds as scalars (pos and neg) ----
    u64 U[RPT], UB[RPT], P[RPT], Q[RPT], FV[RPT];
    float lx0[RPT], lx1[RPT], nx0[RPT], nx1[RPT];
    float ly0[RPT], ly1[RPT], ny0[RPT], ny1[RPT];
#pragma unroll
    for (int k = 0; k < RPT; k++) {
        float uu[2], ll_x[2], ll_y[2];
#pragma unroll
        for (int e = 0; e < 2; e++) {
            const int gi = gi_top + k, gj = gj0 + e;
            const bool ii = (gi >= 0 && gi < HH && gj >= 0 && gj < WW);
            const int idx = base + k * WW + e;
            uu[e]   = ii ? f[idx] : 0.f;
            ll_x[e] = (ii && gi < HH - 1) ? lam[idx + WW] : 0.f;  // bound p(r,c)
            ll_y[e] = (ii && gj < WW - 1) ? lam[idx + 1]  : 0.f;  // bound q(r,c)
        }
        FV[k] = pack2(uu[0], uu[1]);
        U[k] = UB[k] = FV[k];
        P[k] = Q[k] = 0ULL;
        lx0[k] = ll_x[0]; lx1[k] = ll_x[1]; nx0[k] = -ll_x[0]; nx1[k] = -ll_x[1];
        ly0[k] = ll_y[0]; ly1[k] = ll_y[1]; ny0[k] = -ll_y[0]; ny1[k] = -ll_y[1];
    }
    const u64 SIG2 = pack2(SIG, SIG);
    const u64 TAU2 = pack2(TAUc, TAUc);
    const u64 INV2 = pack2(INV, INV);
    const u64 TWO2 = pack2(2.f, 2.f);
    const u64 NEG1 = pack2(-1.f, -1.f);

    __syncthreads();   // zeros complete before targeted writes
    {
        float lo, hi;
#pragma unroll
        for (int k = 0; k < RPT; k++) { unpack2(UB[k], lo, hi); ubE[rb + k][cp] = lo; }
        *(u64*)&ubB[rg][c0] = UB[0];
    }
    __syncthreads();

#pragma unroll 1
    for (int blk = 0; blk < NB; blk++) {
        if (blk) {
            const int sb = blk & 1;
            // ---- publish interior frame (width-TT band inside true tile) ----
#pragma unroll
            for (int k = 0; k < RPT; k++) {
                const int r = rb + k;
                if (r >= TT && r < EXT_H - TT) {
                    float uu[2], uub[2], pp[2], qq[2];
                    unpack2(U[k], uu[0], uu[1]);   unpack2(UB[k], uub[0], uub[1]);
                    unpack2(P[k], pp[0], pp[1]);   unpack2(Q[k],  qq[0],  qq[1]);
#pragma unroll
                    for (int e = 0; e < 2; e++) {
                        const int c = c0 + e;
                        const bool interior = (c >= TT && c < EXT_W - TT);
                        if (interior && (r < 2*TT || r >= EXT_H - 2*TT ||
                                         c < 2*TT || c >= EXT_W - 2*TT)) {
                            const int idx = base + k * WW + e;
                            gU [sb][idx] = uu[e];  gUB[sb][idx] = uub[e];
                            gP [sb][idx] = pp[e];  gQ [sb][idx] = qq[e];
                        }
                    }
                }
            }
            __syncthreads();   // all publishes complete

            // ---- per-image 32-CTA barrier (arrive + spin, monotone) ----
            if (tid == 0) {
                red_rel_add1(&g_arr[img].v);
                const u64 tgt = epoch + 32ULL * (u64)blk;
                while ((long long)(ld_acq(&g_arr[img].v) - tgt) < 0) { }
            }
            __syncthreads();   // release observed; ring reads ordered

            // ---- refresh ring (full state) from neighbors' publishes ----
#pragma unroll
            for (int k = 0; k < RPT; k++) {
                const int r = rb + k;
                const bool kRing = (r < TT || r >= EXT_H - TT ||
                                    c0 < TT || c0 + 1 >= EXT_W - TT);
                if (kRing) {
                    float uu[2], uub[2], pp[2], qq[2];
                    unpack2(U[k], uu[0], uu[1]);   unpack2(UB[k], uub[0], uub[1]);
                    unpack2(P[k], pp[0], pp[1]);   unpack2(Q[k],  qq[0],  qq[1]);
#pragma unroll
                    for (int e = 0; e < 2; e++) {
                        const int c = c0 + e;
                        const int gi = gi_top + k, gj = gj0 + e;
                        const bool ring = (r < TT || r >= EXT_H - TT ||
                                           c < TT || c >= EXT_W - TT);
                        if (ring && gi >= 0 && gi < HH && gj >= 0 && gj < WW) {
                            const int idx = base + k * WW + e;
                            uu[e]  = ldcg(&gU [sb][idx]);
                            uub[e] = ldcg(&gUB[sb][idx]);
                            pp[e]  = ldcg(&gP [sb][idx]);
                            qq[e]  = ldcg(&gQ [sb][idx]);
                            if (e == 0) ubE[r][cp] = uub[0];
                            if (k == 0) ubB[rg][c] = uub[e];
                        }
                    }
                    U[k]  = pack2(uu[0], uu[1]);   UB[k] = pack2(uub[0], uub[1]);
                    P[k]  = pack2(pp[0], pp[1]);   Q[k]  = pack2(qq[0],  qq[1]);
                }
            }
            __syncthreads();
        }

#pragma unroll 1
        for (int s = 0; s < TT; s++) {
            // ---- phase 1: dual update (p, q), packed fma + lane clip ----
            const u64 ubb01 = *(const u64*)&ubB[rg + 1][c0];
#pragma unroll
            for (int k = 0; k < RPT; k++) {
                const u64 ubk  = UB[k];
                const u64 ub_b = (k < RPT - 1) ? UB[k + 1] : ubb01;
                // p += SIG*(ub_below - ub), clip
                const u64 dp = fma2(ubk, NEG1, ub_b);
                P[k] = clip2(fma2(SIG2, dp, P[k]), lx0[k], lx1[k], nx0[k], nx1[k]);
                // q += SIG*(ub_right - ub): right pair = (ub.hi, ubE[r][cp+1])
                float ublo, ubhi; unpack2(ubk, ublo, ubhi);
                const u64 ubq = pack2(ubhi, ubE[rb + k][cp + 1]);
                const u64 dq = fma2(ubk, NEG1, ubq);
                const u64 qk = clip2(fma2(SIG2, dq, Q[k]), ly0[k], ly1[k], ny0[k], ny1[k]);
                Q[k] = qk;
                float qlo, qhi; unpack2(qk, qlo, qhi);
                qO[rb + k][cp + 1] = qhi;
            }
            *(u64*)&pB[rg + 1][c0] = P[RPT - 1];
            __syncthreads();

            // ---- phase 2: primal update (u, ubar), packed ----
            u64 pu01 = *(const u64*)&pB[rg][c0];
#pragma unroll
            for (int k = 0; k < RPT; k++) {
                float qlo, qhi; unpack2(Q[k], qlo, qhi);
                const u64 qw01 = pack2(qO[rb + k][cp], qlo);     // (q_left, q_even)
                const u64 div  = add2(fma2(P[k], NEG1, pu01),    // (pu - p)
                                      fma2(Q[k], NEG1, qw01));   // + (qw - q)
                const u64 inner = fma2(div, NEG1, FV[k]);        // fv - div
                const u64 un = mul2(fma2(TAU2, inner, U[k]), INV2);
                UB[k] = fma2(TWO2, un, mul2(U[k], NEG1));        // 2*un - u
                pu01 = P[k];
                U[k] = un;
                float unlo, unhi; unpack2(UB[k], unlo, unhi);
                ubE[rb + k][cp] = unlo;
            }
            *(u64*)&ubB[rg][c0] = UB[0];
            __syncthreads();
        }
    }

    // ---- write interior result ----
#pragma unroll
    for (int k = 0; k < RPT; k++) {
        const int r = rb + k;
        if (r >= TT && r < EXT_H - TT) {
            float uu[2]; unpack2(U[k], uu[0], uu[1]);
#pragma unroll
            for (int e = 0; e < 2; e++) {
                const int c = c0 + e;
                if (c >= TT && c < EXT_W - TT)
                    out[base + k * WW + e] = uu[e];
            }
        }
    }
}

extern "C" void kernel_launch(void* const* d_in, const int* in_sizes, int n_in,
                              void* d_out, int out_size) {
    const float* f   = (const float*)d_in[0];
    const float* lam = (const float*)d_in[1];
    float* out = (float*)d_out;

    // Cooperative launch only for co-residency (per-image barrier needs all
    // 32 CTAs of an image resident); no grid.sync used.
    void* args[] = { (void*)&f, (void*)&lam, (void*)&out };
    cudaLaunchCooperativeKernel((void*)tv_block,
                                dim3(NCTAS), dim3(NTHREADS),
                                args, 0, 0);
}